// round 5
// baseline (speedup 1.0000x reference)
#include <cuda_runtime.h>

// ---------------- problem constants ----------------
#define TT 4
#define BB 8
#define CC 256
#define NN 2048
#define TBB 32            // T*B
#define ELEMS 16777216    // TB*C*N
#define CNT_D 65536.0     // T*B*N per-channel count

// ---------------- scratch (device globals; no allocation allowed) ----------------
__device__ float g_hq[ELEMS];   // h_q  -> later aliased as attention output s
__device__ float g_hk[ELEMS];   // h_k  -> later aliased as proj pre-activation h2
__device__ float g_hv[ELEMS];   // h_v
__device__ double g_sum[4 * CC];
__device__ double g_sqs[4 * CC];
__device__ float  g_a[4 * CC];
__device__ float  g_b[4 * CC];

// ---------------- zero stats (must run per graph replay) ----------------
__global__ void zero_stats_kernel() {
    for (int j = threadIdx.x; j < 4 * CC; j += blockDim.x) {
        g_sum[j] = 0.0;
        g_sqs[j] = 0.0;
    }
}

// ---------------- GEMM (1x1 conv) + per-channel partial stats ----------------
// H[tb][m][n] = sum_k W[m][k] * X[tb][k][n], X layout [TB][C][N] (row-major, N contig)
// BM=128, BN=128, BK=16, 256 threads, 8x8 micro-tile per thread.
// Double-buffered smem: one __syncthreads() per K-tile, loads overlap FFMAs.
__global__ __launch_bounds__(256) void gemm_bn_kernel(
    const float* __restrict__ X, const float* __restrict__ W,
    float* __restrict__ Hout, int stage)
{
    const int tb  = blockIdx.z;
    const int m0  = blockIdx.y * 128;
    const int n0  = blockIdx.x * 128;
    const int tid = threadIdx.x;
    const int tx  = tid & 15;
    const int ty  = tid >> 4;

    __shared__ float Ws[2][16][132];   // [buf][k][m], padded
    __shared__ float Xs[2][16][128];   // [buf][k][n]

    float acc[8][8];
#pragma unroll
    for (int i = 0; i < 8; ++i)
#pragma unroll
        for (int j = 0; j < 8; ++j) acc[i][j] = 0.0f;

    const float* Xbase = X + (size_t)tb * CC * NN + n0;

    // per-thread load coordinates (2 float4 of W, 2 float4 of X per tile)
    const int wrow0 = tid >> 2;                 // 0..63
    const int wkq   = (tid & 3) * 4;            // 0,4,8,12
    const int xk0   = tid >> 5;                 // 0..7
    const int xn4   = (tid & 31) * 4;           // 0..124

    // prologue: load tile 0 into buffer 0
    {
        float4 w0 = *reinterpret_cast<const float4*>(W + (size_t)(m0 + wrow0) * CC + wkq);
        float4 w1 = *reinterpret_cast<const float4*>(W + (size_t)(m0 + 64 + wrow0) * CC + wkq);
        Ws[0][wkq + 0][wrow0] = w0.x; Ws[0][wkq + 1][wrow0] = w0.y;
        Ws[0][wkq + 2][wrow0] = w0.z; Ws[0][wkq + 3][wrow0] = w0.w;
        Ws[0][wkq + 0][64 + wrow0] = w1.x; Ws[0][wkq + 1][64 + wrow0] = w1.y;
        Ws[0][wkq + 2][64 + wrow0] = w1.z; Ws[0][wkq + 3][64 + wrow0] = w1.w;
        float4 x0 = *reinterpret_cast<const float4*>(Xbase + (size_t)xk0 * NN + xn4);
        float4 x1 = *reinterpret_cast<const float4*>(Xbase + (size_t)(xk0 + 8) * NN + xn4);
        *reinterpret_cast<float4*>(&Xs[0][xk0][xn4]) = x0;
        *reinterpret_cast<float4*>(&Xs[0][xk0 + 8][xn4]) = x1;
    }

    for (int kt = 0; kt < 16; ++kt) {
        const int cur = kt & 1;
        const int nxt = cur ^ 1;
        __syncthreads();   // buffer `cur` fully written; prior readers of `nxt` done

        // issue next tile's loads into the other buffer (overlaps with FFMAs below)
        if (kt + 1 < 16) {
            const int k0 = (kt + 1) * 16;
            float4 w0 = *reinterpret_cast<const float4*>(W + (size_t)(m0 + wrow0) * CC + k0 + wkq);
            float4 w1 = *reinterpret_cast<const float4*>(W + (size_t)(m0 + 64 + wrow0) * CC + k0 + wkq);
            Ws[nxt][wkq + 0][wrow0] = w0.x; Ws[nxt][wkq + 1][wrow0] = w0.y;
            Ws[nxt][wkq + 2][wrow0] = w0.z; Ws[nxt][wkq + 3][wrow0] = w0.w;
            Ws[nxt][wkq + 0][64 + wrow0] = w1.x; Ws[nxt][wkq + 1][64 + wrow0] = w1.y;
            Ws[nxt][wkq + 2][64 + wrow0] = w1.z; Ws[nxt][wkq + 3][64 + wrow0] = w1.w;
            float4 x0 = *reinterpret_cast<const float4*>(Xbase + (size_t)(k0 + xk0) * NN + xn4);
            float4 x1 = *reinterpret_cast<const float4*>(Xbase + (size_t)(k0 + xk0 + 8) * NN + xn4);
            *reinterpret_cast<float4*>(&Xs[nxt][xk0][xn4]) = x0;
            *reinterpret_cast<float4*>(&Xs[nxt][xk0 + 8][xn4]) = x1;
        }

#pragma unroll
        for (int kk = 0; kk < 16; ++kk) {
            float wf[8], xf[8];
            float4 w0 = *reinterpret_cast<const float4*>(&Ws[cur][kk][ty * 8]);
            float4 w1 = *reinterpret_cast<const float4*>(&Ws[cur][kk][ty * 8 + 4]);
            wf[0] = w0.x; wf[1] = w0.y; wf[2] = w0.z; wf[3] = w0.w;
            wf[4] = w1.x; wf[5] = w1.y; wf[6] = w1.z; wf[7] = w1.w;
            float4 xa = *reinterpret_cast<const float4*>(&Xs[cur][kk][tx * 4]);
            float4 xb = *reinterpret_cast<const float4*>(&Xs[cur][kk][64 + tx * 4]);
            xf[0] = xa.x; xf[1] = xa.y; xf[2] = xa.z; xf[3] = xa.w;
            xf[4] = xb.x; xf[5] = xb.y; xf[6] = xb.z; xf[7] = xb.w;
#pragma unroll
            for (int i = 0; i < 8; ++i)
#pragma unroll
                for (int j = 0; j < 8; ++j)
                    acc[i][j] = fmaf(wf[i], xf[j], acc[i][j]);
        }
    }

    // epilogue: store H + per-channel partial sum / sumsq (double atomics)
#pragma unroll
    for (int i = 0; i < 8; ++i) {
        const int row = m0 + ty * 8 + i;
        float* out = Hout + ((size_t)tb * CC + row) * NN + n0;
        float4 v0 = make_float4(acc[i][0], acc[i][1], acc[i][2], acc[i][3]);
        float4 v1 = make_float4(acc[i][4], acc[i][5], acc[i][6], acc[i][7]);
        *reinterpret_cast<float4*>(out + tx * 4) = v0;
        *reinterpret_cast<float4*>(out + 64 + tx * 4) = v1;

        float s = 0.0f, q = 0.0f;
#pragma unroll
        for (int j = 0; j < 8; ++j) {
            s += acc[i][j];
            q += acc[i][j] * acc[i][j];
        }
        // reduce across the 16 tx lanes (xor 1,2,4,8 stays inside 16-lane group)
#pragma unroll
        for (int m = 8; m >= 1; m >>= 1) {
            s += __shfl_xor_sync(0xffffffffu, s, m);
            q += __shfl_xor_sync(0xffffffffu, q, m);
        }
        if (tx == 0) {
            atomicAdd(&g_sum[stage * CC + row], (double)s);
            atomicAdd(&g_sqs[stage * CC + row], (double)q);
        }
    }
}

// ---------------- finalize BN: a = gamma*rsqrt(var+eps), b = beta - mean*a ----------------
__global__ void finalize_stage_kernel(int stage,
                                      const float* __restrict__ gamma,
                                      const float* __restrict__ beta)
{
    int c = threadIdx.x;
    if (c >= CC) return;
    double mean = g_sum[stage * CC + c] / CNT_D;
    double var  = g_sqs[stage * CC + c] / CNT_D - mean * mean;
    double rst  = rsqrt(var + 1e-5);
    double a    = (double)gamma[c] * rst;
    g_a[stage * CC + c] = (float)a;
    g_b[stage * CC + c] = (float)((double)beta[c] - mean * a);
}

// ---------------- attention: spikes -> bit masks -> integer kv -> s (binary, float) --------
// block = (head, tb). Reads g_hq/g_hk/g_hv + g_a/g_b[0..2]; writes s into g_hq (alias-safe:
// each block only touches its own 16-channel slab, all reads complete before writes).
__global__ __launch_bounds__(256) void attn_kernel()
{
    const int head = blockIdx.x;
    const int tb   = blockIdx.y;
    const int c0   = head * 16;
    const int tid  = threadIdx.x;
    const int lane = tid & 31;
    const int wid  = tid >> 5;

    __shared__ unsigned short qm[NN], km[NN], vm[NN];
    __shared__ int   wkv[8][256];
    __shared__ int   kv[256];
    __shared__ float sa[6][16];

    if (tid < 16) {
        sa[0][tid] = g_a[0 * CC + c0 + tid];
        sa[1][tid] = g_b[0 * CC + c0 + tid];
        sa[2][tid] = g_a[1 * CC + c0 + tid];
        sa[3][tid] = g_b[1 * CC + c0 + tid];
        sa[4][tid] = g_a[2 * CC + c0 + tid];
        sa[5][tid] = g_b[2 * CC + c0 + tid];
    }
    __syncthreads();

    const size_t base0 = ((size_t)tb * CC + c0) * NN;

    // phase 1: spike thresholds -> 16-bit masks per token
    for (int n = tid; n < NN; n += 256) {
        unsigned q = 0, k = 0, v = 0;
#pragma unroll
        for (int d = 0; d < 16; ++d) {
            size_t off = base0 + (size_t)d * NN + n;
            if (fmaf(sa[0][d], g_hq[off], sa[1][d]) >= 1.0f) q |= 1u << d;
            if (fmaf(sa[2][d], g_hk[off], sa[3][d]) >= 1.0f) k |= 1u << d;
            if (fmaf(sa[4][d], g_hv[off], sa[5][d]) >= 1.0f) v |= 1u << d;
        }
        qm[n] = (unsigned short)q;
        km[n] = (unsigned short)k;
        vm[n] = (unsigned short)v;
    }
    __syncthreads();

    // phase 2: kv[d][e] = sum_n k[n,d]*v[n,e] via ballot + popcount.
    // lane owns d = lane>>1 and e-block = (lane&1)*8 (static register indexing).
    int cnt[8];
#pragma unroll
    for (int p = 0; p < 8; ++p) cnt[p] = 0;

    const int myd = lane >> 1;
    const int ehalf = lane & 1;
    for (int ch = wid; ch < NN / 32; ch += 8) {
        unsigned kk_ = km[ch * 32 + lane];
        unsigned vv_ = vm[ch * 32 + lane];
        unsigned mykb = 0;
#pragma unroll
        for (int d = 0; d < 16; ++d) {
            unsigned bl = __ballot_sync(0xffffffffu, (kk_ >> d) & 1u);
            if (d == myd) mykb = bl;
        }
        unsigned myvb[8];
#pragma unroll
        for (int e = 0; e < 16; ++e) {
            unsigned bl = __ballot_sync(0xffffffffu, (vv_ >> e) & 1u);
            if ((e >> 3) == ehalf) myvb[e & 7] = bl;
        }
#pragma unroll
        for (int p = 0; p < 8; ++p)
            cnt[p] += __popc(mykb & myvb[p]);
    }
#pragma unroll
    for (int p = 0; p < 8; ++p)
        wkv[wid][myd * 16 + ehalf * 8 + p] = cnt[p];
    __syncthreads();
    {
        int t = 0;
#pragma unroll
        for (int w = 0; w < 8; ++w) t += wkv[w][tid];
        kv[tid] = t;       // kv[d*16+e]
    }
    __syncthreads();

    // phase 3: o = q @ kv; s = (0.25*o >= 0.5) <=> (o >= 2), exact integer.
    for (int n = tid; n < NN; n += 256) {
        unsigned q = qm[n];
        int o[16];
#pragma unroll
        for (int e = 0; e < 16; ++e) o[e] = 0;
        while (q) {
            int d = __ffs(q) - 1;
            q &= q - 1;
            const int* r = &kv[d * 16];
#pragma unroll
            for (int e = 0; e < 16; ++e) o[e] += r[e];
        }
#pragma unroll
        for (int e = 0; e < 16; ++e)
            g_hq[base0 + (size_t)e * NN + n] = (o[e] >= 2) ? 1.0f : 0.0f;
    }
}

// ---------------- final spike: out = (a3*h2 + b3 >= 1) ----------------
__global__ void spike_out_kernel(const float* __restrict__ h2, float* __restrict__ out)
{
    size_t i = ((size_t)blockIdx.x * blockDim.x + threadIdx.x) * 4;
    if (i >= (size_t)ELEMS) return;
    int c = (int)((i / NN) & (CC - 1));
    float a = g_a[3 * CC + c];
    float b = g_b[3 * CC + c];
    float4 h = *reinterpret_cast<const float4*>(h2 + i);
    float4 o;
    o.x = (fmaf(a, h.x, b) >= 1.0f) ? 1.0f : 0.0f;
    o.y = (fmaf(a, h.y, b) >= 1.0f) ? 1.0f : 0.0f;
    o.z = (fmaf(a, h.z, b) >= 1.0f) ? 1.0f : 0.0f;
    o.w = (fmaf(a, h.w, b) >= 1.0f) ? 1.0f : 0.0f;
    *reinterpret_cast<float4*>(out + i) = o;
}

// ---------------- launch ----------------
extern "C" void kernel_launch(void* const* d_in, const int* in_sizes, int n_in,
                              void* d_out, int out_size)
{
    const float* x    = (const float*)d_in[0];
    const float* y    = (const float*)d_in[1];
    const float* q_w  = (const float*)d_in[2];
    const float* q_g  = (const float*)d_in[3];
    const float* q_b  = (const float*)d_in[4];
    const float* k_w  = (const float*)d_in[5];
    const float* k_g  = (const float*)d_in[6];
    const float* k_b  = (const float*)d_in[7];
    const float* v_w  = (const float*)d_in[8];
    const float* v_g  = (const float*)d_in[9];
    const float* v_b  = (const float*)d_in[10];
    const float* p_w  = (const float*)d_in[11];
    const float* p_g  = (const float*)d_in[12];
    const float* p_b  = (const float*)d_in[13];
    float* out = (float*)d_out;

    // resolve scratch pointers every call (host API, not stream-ordered: capture-safe)
    float* hq = nullptr; float* hk = nullptr; float* hv = nullptr;
    cudaGetSymbolAddress((void**)&hq, g_hq);
    cudaGetSymbolAddress((void**)&hk, g_hk);
    cudaGetSymbolAddress((void**)&hv, g_hv);

    zero_stats_kernel<<<1, 256>>>();

    dim3 gg(NN / 128, CC / 128, TBB);   // (16, 2, 32)
    gemm_bn_kernel<<<gg, 256>>>(x, q_w, hq, 0);
    gemm_bn_kernel<<<gg, 256>>>(y, k_w, hk, 1);
    gemm_bn_kernel<<<gg, 256>>>(y, v_w, hv, 2);

    finalize_stage_kernel<<<1, 256>>>(0, q_g, q_b);
    finalize_stage_kernel<<<1, 256>>>(1, k_g, k_b);
    finalize_stage_kernel<<<1, 256>>>(2, v_g, v_b);

    attn_kernel<<<dim3(16, TBB), 256>>>();          // writes s into g_hq

    gemm_bn_kernel<<<gg, 256>>>(hq, p_w, hk, 3);    // proj: h2 into g_hk
    finalize_stage_kernel<<<1, 256>>>(3, p_g, p_b);

    spike_out_kernel<<<ELEMS / 4 / 256, 256>>>(hk, out);
}

// round 7
// speedup vs baseline: 1.0035x; 1.0035x over previous
#include <cuda_runtime.h>

// ---------------- problem constants ----------------
#define TT 4
#define BB 8
#define CC 256
#define NN 2048
#define TBB 32            // T*B
#define ELEMS 16777216    // TB*C*N
#define CNT_D 65536.0     // T*B*N per-channel count

// ---------------- scratch (device globals; no allocation allowed) ----------------
__device__ float g_hq[ELEMS];   // h_q  -> later aliased as attention output s
__device__ float g_hk[ELEMS];   // h_k  -> later aliased as proj pre-activation h2
__device__ float g_hv[ELEMS];   // h_v
__device__ double g_sum[4 * CC];
__device__ double g_sqs[4 * CC];
__device__ float  g_a[4 * CC];
__device__ float  g_b[4 * CC];

// ---------------- zero stats (must run per graph replay) ----------------
__global__ void zero_stats_kernel() {
    for (int j = threadIdx.x; j < 4 * CC; j += blockDim.x) {
        g_sum[j] = 0.0;
        g_sqs[j] = 0.0;
    }
}

// ---------------- GEMM (1x1 conv) + per-channel partial stats ----------------
// H[tb][m][n] = sum_k W[m][k] * X[tb][k][n], X layout [TB][C][N] (row-major, N contig)
// BM=128, BN=128, BK=16, 256 threads, 8x8 micro-tile per thread.
// Double-buffered smem: one __syncthreads() per K-tile, loads overlap FFMAs.
__global__ __launch_bounds__(256) void gemm_bn_kernel(
    const float* __restrict__ X, const float* __restrict__ W,
    float* __restrict__ Hout, int stage)
{
    const int tb  = blockIdx.z;
    const int m0  = blockIdx.y * 128;
    const int n0  = blockIdx.x * 128;
    const int tid = threadIdx.x;
    const int tx  = tid & 15;
    const int ty  = tid >> 4;

    __shared__ float Ws[2][16][132];   // [buf][k][m], padded
    __shared__ float Xs[2][16][128];   // [buf][k][n]

    float acc[8][8];
#pragma unroll
    for (int i = 0; i < 8; ++i)
#pragma unroll
        for (int j = 0; j < 8; ++j) acc[i][j] = 0.0f;

    const float* Xbase = X + (size_t)tb * CC * NN + n0;

    // per-thread load coordinates (2 float4 of W, 2 float4 of X per tile)
    const int wrow0 = tid >> 2;                 // 0..63
    const int wkq   = (tid & 3) * 4;            // 0,4,8,12
    const int xk0   = tid >> 5;                 // 0..7
    const int xn4   = (tid & 31) * 4;           // 0..124

    // prologue: load tile 0 into buffer 0
    {
        float4 w0 = *reinterpret_cast<const float4*>(W + (size_t)(m0 + wrow0) * CC + wkq);
        float4 w1 = *reinterpret_cast<const float4*>(W + (size_t)(m0 + 64 + wrow0) * CC + wkq);
        Ws[0][wkq + 0][wrow0] = w0.x; Ws[0][wkq + 1][wrow0] = w0.y;
        Ws[0][wkq + 2][wrow0] = w0.z; Ws[0][wkq + 3][wrow0] = w0.w;
        Ws[0][wkq + 0][64 + wrow0] = w1.x; Ws[0][wkq + 1][64 + wrow0] = w1.y;
        Ws[0][wkq + 2][64 + wrow0] = w1.z; Ws[0][wkq + 3][64 + wrow0] = w1.w;
        float4 x0 = *reinterpret_cast<const float4*>(Xbase + (size_t)xk0 * NN + xn4);
        float4 x1 = *reinterpret_cast<const float4*>(Xbase + (size_t)(xk0 + 8) * NN + xn4);
        *reinterpret_cast<float4*>(&Xs[0][xk0][xn4]) = x0;
        *reinterpret_cast<float4*>(&Xs[0][xk0 + 8][xn4]) = x1;
    }

    for (int kt = 0; kt < 16; ++kt) {
        const int cur = kt & 1;
        const int nxt = cur ^ 1;
        __syncthreads();   // buffer `cur` fully written; prior readers of `nxt` done

        // issue next tile's loads into the other buffer (overlaps with FFMAs below)
        if (kt + 1 < 16) {
            const int k0 = (kt + 1) * 16;
            float4 w0 = *reinterpret_cast<const float4*>(W + (size_t)(m0 + wrow0) * CC + k0 + wkq);
            float4 w1 = *reinterpret_cast<const float4*>(W + (size_t)(m0 + 64 + wrow0) * CC + k0 + wkq);
            Ws[nxt][wkq + 0][wrow0] = w0.x; Ws[nxt][wkq + 1][wrow0] = w0.y;
            Ws[nxt][wkq + 2][wrow0] = w0.z; Ws[nxt][wkq + 3][wrow0] = w0.w;
            Ws[nxt][wkq + 0][64 + wrow0] = w1.x; Ws[nxt][wkq + 1][64 + wrow0] = w1.y;
            Ws[nxt][wkq + 2][64 + wrow0] = w1.z; Ws[nxt][wkq + 3][64 + wrow0] = w1.w;
            float4 x0 = *reinterpret_cast<const float4*>(Xbase + (size_t)(k0 + xk0) * NN + xn4);
            float4 x1 = *reinterpret_cast<const float4*>(Xbase + (size_t)(k0 + xk0 + 8) * NN + xn4);
            *reinterpret_cast<float4*>(&Xs[nxt][xk0][xn4]) = x0;
            *reinterpret_cast<float4*>(&Xs[nxt][xk0 + 8][xn4]) = x1;
        }

#pragma unroll
        for (int kk = 0; kk < 16; ++kk) {
            float wf[8], xf[8];
            float4 w0 = *reinterpret_cast<const float4*>(&Ws[cur][kk][ty * 8]);
            float4 w1 = *reinterpret_cast<const float4*>(&Ws[cur][kk][ty * 8 + 4]);
            wf[0] = w0.x; wf[1] = w0.y; wf[2] = w0.z; wf[3] = w0.w;
            wf[4] = w1.x; wf[5] = w1.y; wf[6] = w1.z; wf[7] = w1.w;
            float4 xa = *reinterpret_cast<const float4*>(&Xs[cur][kk][tx * 4]);
            float4 xb = *reinterpret_cast<const float4*>(&Xs[cur][kk][64 + tx * 4]);
            xf[0] = xa.x; xf[1] = xa.y; xf[2] = xa.z; xf[3] = xa.w;
            xf[4] = xb.x; xf[5] = xb.y; xf[6] = xb.z; xf[7] = xb.w;
#pragma unroll
            for (int i = 0; i < 8; ++i)
#pragma unroll
                for (int j = 0; j < 8; ++j)
                    acc[i][j] = fmaf(wf[i], xf[j], acc[i][j]);
        }
    }

    // epilogue: store H + per-channel partial sum / sumsq (double atomics)
#pragma unroll
    for (int i = 0; i < 8; ++i) {
        const int row = m0 + ty * 8 + i;
        float* out = Hout + ((size_t)tb * CC + row) * NN + n0;
        float4 v0 = make_float4(acc[i][0], acc[i][1], acc[i][2], acc[i][3]);
        float4 v1 = make_float4(acc[i][4], acc[i][5], acc[i][6], acc[i][7]);
        *reinterpret_cast<float4*>(out + tx * 4) = v0;
        *reinterpret_cast<float4*>(out + 64 + tx * 4) = v1;

        float s = 0.0f, q = 0.0f;
#pragma unroll
        for (int j = 0; j < 8; ++j) {
            s += acc[i][j];
            q += acc[i][j] * acc[i][j];
        }
        // reduce across the 16 tx lanes (xor 1,2,4,8 stays inside 16-lane group)
#pragma unroll
        for (int m = 8; m >= 1; m >>= 1) {
            s += __shfl_xor_sync(0xffffffffu, s, m);
            q += __shfl_xor_sync(0xffffffffu, q, m);
        }
        if (tx == 0) {
            atomicAdd(&g_sum[stage * CC + row], (double)s);
            atomicAdd(&g_sqs[stage * CC + row], (double)q);
        }
    }
}

// ---------------- finalize BN: a = gamma*rsqrt(var+eps), b = beta - mean*a ----------------
__global__ void finalize_stage_kernel(int stage,
                                      const float* __restrict__ gamma,
                                      const float* __restrict__ beta)
{
    int c = threadIdx.x;
    if (c >= CC) return;
    double mean = g_sum[stage * CC + c] / CNT_D;
    double var  = g_sqs[stage * CC + c] / CNT_D - mean * mean;
    double rst  = rsqrt(var + 1e-5);
    double a    = (double)gamma[c] * rst;
    g_a[stage * CC + c] = (float)a;
    g_b[stage * CC + c] = (float)((double)beta[c] - mean * a);
}

// ---------------- attention: spikes -> bit masks -> integer kv -> s (binary, float) --------
// block = (head, tb). Reads g_hq/g_hk/g_hv + g_a/g_b[0..2]; writes s into g_hq (alias-safe:
// each block only touches its own 16-channel slab, all reads complete before writes).
__global__ __launch_bounds__(256) void attn_kernel()
{
    const int head = blockIdx.x;
    const int tb   = blockIdx.y;
    const int c0   = head * 16;
    const int tid  = threadIdx.x;
    const int lane = tid & 31;
    const int wid  = tid >> 5;

    __shared__ unsigned short qm[NN], km[NN], vm[NN];
    __shared__ int   wkv[8][256];
    __shared__ int   kv[256];
    __shared__ float sa[6][16];

    if (tid < 16) {
        sa[0][tid] = g_a[0 * CC + c0 + tid];
        sa[1][tid] = g_b[0 * CC + c0 + tid];
        sa[2][tid] = g_a[1 * CC + c0 + tid];
        sa[3][tid] = g_b[1 * CC + c0 + tid];
        sa[4][tid] = g_a[2 * CC + c0 + tid];
        sa[5][tid] = g_b[2 * CC + c0 + tid];
    }
    __syncthreads();

    const size_t base0 = ((size_t)tb * CC + c0) * NN;

    // phase 1: spike thresholds -> 16-bit masks per token
    for (int n = tid; n < NN; n += 256) {
        unsigned q = 0, k = 0, v = 0;
#pragma unroll
        for (int d = 0; d < 16; ++d) {
            size_t off = base0 + (size_t)d * NN + n;
            if (fmaf(sa[0][d], g_hq[off], sa[1][d]) >= 1.0f) q |= 1u << d;
            if (fmaf(sa[2][d], g_hk[off], sa[3][d]) >= 1.0f) k |= 1u << d;
            if (fmaf(sa[4][d], g_hv[off], sa[5][d]) >= 1.0f) v |= 1u << d;
        }
        qm[n] = (unsigned short)q;
        km[n] = (unsigned short)k;
        vm[n] = (unsigned short)v;
    }
    __syncthreads();

    // phase 2: kv[d][e] = sum_n k[n,d]*v[n,e] via ballot + popcount.
    // lane owns d = lane>>1 and e-block = (lane&1)*8 (static register indexing).
    int cnt[8];
#pragma unroll
    for (int p = 0; p < 8; ++p) cnt[p] = 0;

    const int myd = lane >> 1;
    const int ehalf = lane & 1;
    for (int ch = wid; ch < NN / 32; ch += 8) {
        unsigned kk_ = km[ch * 32 + lane];
        unsigned vv_ = vm[ch * 32 + lane];
        unsigned mykb = 0;
#pragma unroll
        for (int d = 0; d < 16; ++d) {
            unsigned bl = __ballot_sync(0xffffffffu, (kk_ >> d) & 1u);
            if (d == myd) mykb = bl;
        }
        unsigned myvb[8];
#pragma unroll
        for (int e = 0; e < 16; ++e) {
            unsigned bl = __ballot_sync(0xffffffffu, (vv_ >> e) & 1u);
            if ((e >> 3) == ehalf) myvb[e & 7] = bl;
        }
#pragma unroll
        for (int p = 0; p < 8; ++p)
            cnt[p] += __popc(mykb & myvb[p]);
    }
#pragma unroll
    for (int p = 0; p < 8; ++p)
        wkv[wid][myd * 16 + ehalf * 8 + p] = cnt[p];
    __syncthreads();
    {
        int t = 0;
#pragma unroll
        for (int w = 0; w < 8; ++w) t += wkv[w][tid];
        kv[tid] = t;       // kv[d*16+e]
    }
    __syncthreads();

    // phase 3: o = q @ kv; s = (0.25*o >= 0.5) <=> (o >= 2), exact integer.
    for (int n = tid; n < NN; n += 256) {
        unsigned q = qm[n];
        int o[16];
#pragma unroll
        for (int e = 0; e < 16; ++e) o[e] = 0;
        while (q) {
            int d = __ffs(q) - 1;
            q &= q - 1;
            const int* r = &kv[d * 16];
#pragma unroll
            for (int e = 0; e < 16; ++e) o[e] += r[e];
        }
#pragma unroll
        for (int e = 0; e < 16; ++e)
            g_hq[base0 + (size_t)e * NN + n] = (o[e] >= 2) ? 1.0f : 0.0f;
    }
}

// ---------------- final spike: out = (a3*h2 + b3 >= 1) ----------------
__global__ void spike_out_kernel(const float* __restrict__ h2, float* __restrict__ out)
{
    size_t i = ((size_t)blockIdx.x * blockDim.x + threadIdx.x) * 4;
    if (i >= (size_t)ELEMS) return;
    int c = (int)((i / NN) & (CC - 1));
    float a = g_a[3 * CC + c];
    float b = g_b[3 * CC + c];
    float4 h = *reinterpret_cast<const float4*>(h2 + i);
    float4 o;
    o.x = (fmaf(a, h.x, b) >= 1.0f) ? 1.0f : 0.0f;
    o.y = (fmaf(a, h.y, b) >= 1.0f) ? 1.0f : 0.0f;
    o.z = (fmaf(a, h.z, b) >= 1.0f) ? 1.0f : 0.0f;
    o.w = (fmaf(a, h.w, b) >= 1.0f) ? 1.0f : 0.0f;
    *reinterpret_cast<float4*>(out + i) = o;
}

// ---------------- launch ----------------
extern "C" void kernel_launch(void* const* d_in, const int* in_sizes, int n_in,
                              void* d_out, int out_size)
{
    const float* x    = (const float*)d_in[0];
    const float* y    = (const float*)d_in[1];
    const float* q_w  = (const float*)d_in[2];
    const float* q_g  = (const float*)d_in[3];
    const float* q_b  = (const float*)d_in[4];
    const float* k_w  = (const float*)d_in[5];
    const float* k_g  = (const float*)d_in[6];
    const float* k_b  = (const float*)d_in[7];
    const float* v_w  = (const float*)d_in[8];
    const float* v_g  = (const float*)d_in[9];
    const float* v_b  = (const float*)d_in[10];
    const float* p_w  = (const float*)d_in[11];
    const float* p_g  = (const float*)d_in[12];
    const float* p_b  = (const float*)d_in[13];
    float* out = (float*)d_out;

    // resolve scratch pointers every call (host API, not stream-ordered: capture-safe)
    float* hq = nullptr; float* hk = nullptr; float* hv = nullptr;
    cudaGetSymbolAddress((void**)&hq, g_hq);
    cudaGetSymbolAddress((void**)&hk, g_hk);
    cudaGetSymbolAddress((void**)&hv, g_hv);

    zero_stats_kernel<<<1, 256>>>();

    dim3 gg(NN / 128, CC / 128, TBB);   // (16, 2, 32)
    gemm_bn_kernel<<<gg, 256>>>(x, q_w, hq, 0);
    gemm_bn_kernel<<<gg, 256>>>(y, k_w, hk, 1);
    gemm_bn_kernel<<<gg, 256>>>(y, v_w, hv, 2);

    finalize_stage_kernel<<<1, 256>>>(0, q_g, q_b);
    finalize_stage_kernel<<<1, 256>>>(1, k_g, k_b);
    finalize_stage_kernel<<<1, 256>>>(2, v_g, v_b);

    attn_kernel<<<dim3(16, TBB), 256>>>();          // writes s into g_hq

    gemm_bn_kernel<<<gg, 256>>>(hq, p_w, hk, 3);    // proj: h2 into g_hk
    finalize_stage_kernel<<<1, 256>>>(3, p_g, p_b);

    spike_out_kernel<<<ELEMS / 4 / 256, 256>>>(hk, out);
}